// round 4
// baseline (speedup 1.0000x reference)
#include <cuda_runtime.h>

#define BB 16
#define NN 2048
#define KK 20
#define KC 26               // phase-A candidate count (margin 6)
#define NEg (BB*NN*KK)      // 655360 edges
#define EPSV 1e-5f

// ---------------- scratch (static device allocations) ----------------
__device__ float g_h1[41943040];          // NEg*64
__device__ float g_h2[41943040];
__device__ int   g_idx[NEg];
__device__ float g_x1[BB*NN*64];
__device__ float g_x2[BB*NN*64];
__device__ float g_x3[BB*NN*64];
__device__ float g_sq[BB*NN];
__device__ float g_ypre[33554432];        // B*N*1024
__device__ double g_acc[6*2048];          // per layer: sum[ C ], sumsq[ C ]
__device__ float g_scale[6*1024];
__device__ float g_shift[6*1024];

__global__ void zero_acc_kernel() {
    int i = blockIdx.x*256 + threadIdx.x;
    if (i < 6*2048) g_acc[i] = 0.0;
}

// squared norms from raw x (B,3,N), fp32 (phase-A screening only)
__global__ void sqx_kernel(const float* __restrict__ x){
    int i = blockIdx.x*256 + threadIdx.x;           // i = b*NN + n
    if (i < BB*NN){
        int b = i >> 11, n = i & (NN-1);
        const float* xb = x + (size_t)b*3*NN;
        float a=xb[n], c=xb[NN+n], d=xb[2*NN+n];
        g_sq[i] = a*a + c*c + d*d;
    }
}

// squared norms from 64-channel point features, fp32 (phase-A screening only)
__global__ void sq64_kernel(int sel){
    const float* pts = (sel==1) ? g_x1 : g_x2;
    int i = blockIdx.x*128 + threadIdx.x;           // point index
    if (i < BB*NN){
        const float4* p = reinterpret_cast<const float4*>(pts + ((size_t)i<<6));
        float s = 0.f;
#pragma unroll
        for (int q=0;q<16;q++){
            float4 v = p[q];
            s += v.x*v.x + v.y*v.y + v.z*v.z + v.w*v.w;
        }
        g_sq[i] = s;
    }
}

// ---------------- KNN two-phase: fp32 screen top-26, fp64 exact rerank -> top-20 ----------------
template<int C>
__global__ void knn_kernel(const float* __restrict__ ext, int sel, int sB, int sN, int sC)
{
    const float* pts = (sel==0) ? ext : (sel==1 ? g_x1 : g_x2);
    __shared__ float tile[128][(C==3)?4:68];
    __shared__ float sqs[128];
    int b = blockIdx.y;
    int row = blockIdx.x*128 + threadIdx.x;
    const float* base = pts + (size_t)b * sB;
    const float* sqb  = g_sq + (size_t)b * NN;

    float p[C];
#pragma unroll
    for (int c=0;c<C;c++) p[c] = base[(size_t)row*sN + (size_t)c*sC];
    float sp = sqb[row];

    float bd[KC]; int bi[KC];
#pragma unroll
    for (int i=0;i<KC;i++){ bd[i]=-3.4e38f; bi[i]=0; }
    float worst = -3.4e38f;

    for (int t=0;t<NN;t+=128) {
        __syncthreads();
        if (C==3) {
            for (int i=threadIdx.x;i<128*3;i+=128){
                int c=i>>7, col=i&127;
                tile[col][c] = base[(size_t)(t+col)*sN + (size_t)c*sC];
            }
        } else {
            for (int i=threadIdx.x;i<128*C;i+=128){
                int col=i/C, c=i-col*C;
                tile[col][c] = base[(size_t)(t+col)*sN + (size_t)c*sC];
            }
        }
        sqs[threadIdx.x] = sqb[t+threadIdx.x];
        __syncthreads();
        for (int j=0;j<128;j++) {
            float dot=0.f;
            if (C==3) {
                dot = p[0]*tile[j][0]+p[1]*tile[j][1]+p[2]*tile[j][2];
            } else {
#pragma unroll
                for (int cq=0;cq<C/4;cq++){
                    float4 tv = *reinterpret_cast<const float4*>(&tile[j][cq*4]);
                    dot += p[cq*4+0]*tv.x; dot += p[cq*4+1]*tv.y;
                    dot += p[cq*4+2]*tv.z; dot += p[cq*4+3]*tv.w;
                }
            }
            float d = 2.f*dot - sp - sqs[j];
            if (d > worst) {
                int pos = KC-1;
                while (pos>0 && bd[pos-1]<d){ bd[pos]=bd[pos-1]; bi[pos]=bi[pos-1]; pos--; }
                bd[pos]=d; bi[pos]=t+j;
                worst = bd[KC-1];
            }
        }
    }

    // ---- phase B: exact (double) rerank of the 26 candidates ----
    double spd = 0.0;
#pragma unroll
    for (int c=0;c<C;c++) spd += (double)p[c]*(double)p[c];

    double sd[KK]; int si[KK];
#pragma unroll
    for (int i=0;i<KK;i++){ sd[i]=-1.0e300; si[i]=0x7fffffff; }

    for (int i=0;i<KC;i++){
        int q = bi[i];
        double dot=0.0, qsq=0.0;
#pragma unroll 4
        for (int c=0;c<C;c++){
            double qv = (double)base[(size_t)q*sN + (size_t)c*sC];
            dot += (double)p[c]*qv;
            qsq += qv*qv;
        }
        double dd = 2.0*dot - spd - qsq;
        // insert (dd, q) into top-20, value desc, tie -> smaller index first
        if (dd > sd[KK-1] || (dd == sd[KK-1] && q < si[KK-1])){
            int pos = KK-1;
            while (pos>0 && (sd[pos-1]<dd || (sd[pos-1]==dd && si[pos-1]>q))){
                sd[pos]=sd[pos-1]; si[pos]=si[pos-1]; pos--;
            }
            sd[pos]=dd; si[pos]=q;
        }
    }

    int* o = g_idx + ((size_t)b*NN + row)*KK;
#pragma unroll
    for (int i=0;i<KK;i++) o[i]=si[i];
}

// ---------------- conv1: edge feature (6) -> 64, from raw x (B,3,N) ----------------
__global__ void conv1_kernel(const float* __restrict__ x, const float* __restrict__ W1)
{
    __shared__ float f[64][6];
    int tid = threadIdx.x;
    int eb = blockIdx.x*64;
    for (int i=tid;i<384;i+=256){
        int el = i/6, c = i-el*6;
        int e = eb + el;
        int bn = e/KK;
        int n = bn & (NN-1);
        int b = bn >> 11;
        const float* xb = x + (size_t)b*3*NN;
        float v;
        if (c<3){ int nb = g_idx[e]; v = xb[c*NN+nb]-xb[c*NN+n]; }
        else    { v = xb[(c-3)*NN+n]; }
        f[el][c]=v;
    }
    int o = tid & 63;
    int eg = tid >> 6;
    float w0=W1[o*6+0],w1=W1[o*6+1],w2=W1[o*6+2],w3=W1[o*6+3],w4=W1[o*6+4],w5=W1[o*6+5];
    __syncthreads();
    for (int r=0;r<16;r++){
        int el = eg*16+r;
        float s = f[el][0]*w0+f[el][1]*w1+f[el][2]*w2+f[el][3]*w3+f[el][4]*w4+f[el][5]*w5;
        g_h1[((size_t)(eb+el)<<6)+o]=s;
    }
}

// ---------------- GEMM 64->64 with fused BN+lrelu on the input ----------------
__global__ void conv_gemm64_kernel(int sel_in, int layer, const float* __restrict__ W, int sel_out)
{
    const float* hin  = sel_in==0 ? g_h1 : g_h2;
    float* hout       = sel_out==0 ? g_h1 : g_h2;
    const float* scale = g_scale + layer*1024;
    const float* shift = g_shift + layer*1024;
    __shared__ float As[64][65];
    __shared__ float Ws[64][65];
    int tid = threadIdx.x;
    int eb = blockIdx.x*64;
    for (int i=tid;i<4096;i+=256){ int o=i>>6,k=i&63; Ws[k][o]=W[(o<<6)+k]; }
    for (int i=tid;i<4096;i+=256){
        int e=i>>6,k=i&63;
        float v = hin[((size_t)(eb+e)<<6)+k]*scale[k]+shift[k];
        As[k][e] = v>0.f ? v : 0.2f*v;
    }
    __syncthreads();
    int tx=tid&15, ty=tid>>4;
    float acc[4][4];
#pragma unroll
    for (int j=0;j<4;j++){
#pragma unroll
        for (int i=0;i<4;i++) acc[j][i]=0.f;
    }
#pragma unroll 8
    for (int k=0;k<64;k++){
        float a0=As[k][ty*4+0],a1=As[k][ty*4+1],a2=As[k][ty*4+2],a3=As[k][ty*4+3];
        float b0=Ws[k][tx*4+0],b1=Ws[k][tx*4+1],b2=Ws[k][tx*4+2],b3=Ws[k][tx*4+3];
        acc[0][0]+=a0*b0; acc[0][1]+=a0*b1; acc[0][2]+=a0*b2; acc[0][3]+=a0*b3;
        acc[1][0]+=a1*b0; acc[1][1]+=a1*b1; acc[1][2]+=a1*b2; acc[1][3]+=a1*b3;
        acc[2][0]+=a2*b0; acc[2][1]+=a2*b1; acc[2][2]+=a2*b2; acc[2][3]+=a2*b3;
        acc[3][0]+=a3*b0; acc[3][1]+=a3*b1; acc[3][2]+=a3*b2; acc[3][3]+=a3*b3;
    }
#pragma unroll
    for (int j=0;j<4;j++){
        float4 v = make_float4(acc[j][0],acc[j][1],acc[j][2],acc[j][3]);
        *reinterpret_cast<float4*>(&hout[((size_t)(eb+ty*4+j)<<6)+(tx<<2)]) = v;
    }
}

// ---------------- GEMM: edge feature (128, gathered on the fly) -> 64 ----------------
__global__ void conv_edge128_kernel(int sel_pts, const float* __restrict__ W)
{
    const float* pts = sel_pts==1 ? g_x1 : g_x2;
    __shared__ float As[64][65];
    __shared__ float Ws[64][65];
    __shared__ int s_cen[64], s_nbr[64];
    int tid=threadIdx.x, eb=blockIdx.x*64;
    if (tid<64){
        int e = eb+tid;
        int bn = e/KK;
        s_cen[tid]=bn;
        s_nbr[tid]=(bn & ~(NN-1)) + g_idx[e];
    }
    int tx=tid&15, ty=tid>>4;
    float acc[4][4];
#pragma unroll
    for (int j=0;j<4;j++){
#pragma unroll
        for (int i=0;i<4;i++) acc[j][i]=0.f;
    }
    for (int half=0; half<2; half++){
        __syncthreads();
        for (int i=tid;i<4096;i+=256){ int o=i>>6,k=i&63; Ws[k][o]=W[o*128 + (half<<6) + k]; }
        for (int i=tid;i<4096;i+=256){
            int e=i>>6,k=i&63;
            float v;
            if (half==0) v = pts[((size_t)s_nbr[e]<<6)+k] - pts[((size_t)s_cen[e]<<6)+k];
            else         v = pts[((size_t)s_cen[e]<<6)+k];
            As[k][e]=v;
        }
        __syncthreads();
#pragma unroll 8
        for (int k=0;k<64;k++){
            float a0=As[k][ty*4+0],a1=As[k][ty*4+1],a2=As[k][ty*4+2],a3=As[k][ty*4+3];
            float b0=Ws[k][tx*4+0],b1=Ws[k][tx*4+1],b2=Ws[k][tx*4+2],b3=Ws[k][tx*4+3];
            acc[0][0]+=a0*b0; acc[0][1]+=a0*b1; acc[0][2]+=a0*b2; acc[0][3]+=a0*b3;
            acc[1][0]+=a1*b0; acc[1][1]+=a1*b1; acc[1][2]+=a1*b2; acc[1][3]+=a1*b3;
            acc[2][0]+=a2*b0; acc[2][1]+=a2*b1; acc[2][2]+=a2*b2; acc[2][3]+=a2*b3;
            acc[3][0]+=a3*b0; acc[3][1]+=a3*b1; acc[3][2]+=a3*b2; acc[3][3]+=a3*b3;
        }
    }
#pragma unroll
    for (int j=0;j<4;j++){
        float4 v = make_float4(acc[j][0],acc[j][1],acc[j][2],acc[j][3]);
        *reinterpret_cast<float4*>(&g_h1[((size_t)(eb+ty*4+j)<<6)+(tx<<2)]) = v;
    }
}

// ---------------- conv6: cat[x1,x2,x3] (192) -> 1024 ----------------
__global__ void conv6_kernel(const float* __restrict__ W6)
{
    __shared__ float As[64][65];
    __shared__ float Ws[64][65];
    int tid=threadIdx.x;
    int rb = blockIdx.x*64;
    int ob = blockIdx.y*64;
    int tx=tid&15, ty=tid>>4;
    float acc[4][4];
#pragma unroll
    for (int j=0;j<4;j++){
#pragma unroll
        for (int i=0;i<4;i++) acc[j][i]=0.f;
    }
    for (int t=0;t<3;t++){
        const float* src = (t==0)? g_x1 : (t==1)? g_x2 : g_x3;
        __syncthreads();
        for (int i=tid;i<4096;i+=256){ int o=i>>6,k=i&63; Ws[k][o]=W6[(size_t)(ob+o)*192 + t*64 + k]; }
        for (int i=tid;i<4096;i+=256){ int r=i>>6,k=i&63; As[k][r]=src[((size_t)(rb+r)<<6)+k]; }
        __syncthreads();
#pragma unroll 8
        for (int k=0;k<64;k++){
            float a0=As[k][ty*4+0],a1=As[k][ty*4+1],a2=As[k][ty*4+2],a3=As[k][ty*4+3];
            float b0=Ws[k][tx*4+0],b1=Ws[k][tx*4+1],b2=Ws[k][tx*4+2],b3=Ws[k][tx*4+3];
            acc[0][0]+=a0*b0; acc[0][1]+=a0*b1; acc[0][2]+=a0*b2; acc[0][3]+=a0*b3;
            acc[1][0]+=a1*b0; acc[1][1]+=a1*b1; acc[1][2]+=a1*b2; acc[1][3]+=a1*b3;
            acc[2][0]+=a2*b0; acc[2][1]+=a2*b1; acc[2][2]+=a2*b2; acc[2][3]+=a2*b3;
            acc[3][0]+=a3*b0; acc[3][1]+=a3*b1; acc[3][2]+=a3*b2; acc[3][3]+=a3*b3;
        }
    }
#pragma unroll
    for (int j=0;j<4;j++){
        float4 v = make_float4(acc[j][0],acc[j][1],acc[j][2],acc[j][3]);
        *reinterpret_cast<float4*>(&g_ypre[(size_t)(rb+ty*4+j)*1024 + ob + (tx<<2)]) = v;
    }
}

// ---------------- per-channel sum / sumsq (double) ----------------
__global__ void stats_kernel(int sel, int layer, int n4, int Cdiv4)
{
    const float* data = sel==0 ? g_h1 : (sel==1 ? g_h2 : g_ypre);
    double* acc = g_acc + layer*2048;
    __shared__ double ss[2048];
    int C = Cdiv4<<2;
    int tid=threadIdx.x;
    for (int i=tid;i<2*C;i+=256) ss[i]=0.0;
    __syncthreads();
    int cq = (tid & (Cdiv4-1))<<2;
    double s0=0,s1=0,s2=0,s3=0,q0=0,q1=0,q2=0,q3=0;
    const float4* d4 = reinterpret_cast<const float4*>(data);
    for (int i=blockIdx.x*256+tid; i<n4; i+=gridDim.x*256){
        float4 v = d4[i];
        s0+=v.x; s1+=v.y; s2+=v.z; s3+=v.w;
        q0+=(double)v.x*v.x; q1+=(double)v.y*v.y; q2+=(double)v.z*v.z; q3+=(double)v.w*v.w;
    }
    atomicAdd(&ss[cq+0],s0); atomicAdd(&ss[cq+1],s1);
    atomicAdd(&ss[cq+2],s2); atomicAdd(&ss[cq+3],s3);
    atomicAdd(&ss[C+cq+0],q0); atomicAdd(&ss[C+cq+1],q1);
    atomicAdd(&ss[C+cq+2],q2); atomicAdd(&ss[C+cq+3],q3);
    __syncthreads();
    for (int i=tid;i<2*C;i+=256) atomicAdd(&acc[i], ss[i]);
}

__global__ void finalize_kernel(int layer, const float* __restrict__ g,
                                const float* __restrict__ bparam, float inv, int C)
{
    int c = threadIdx.x + blockIdx.x*blockDim.x;
    if (c<C){
        const double* acc = g_acc + layer*2048;
        double mean = acc[c]*(double)inv;
        double var  = acc[C+c]*(double)inv - mean*mean;
        float is = rsqrtf((float)var + EPSV)*g[c];
        g_scale[layer*1024+c]=is;
        g_shift[layer*1024+c]=bparam[c]-(float)mean*is;
    }
}

// ---------------- BN+lrelu then max over k=20 ----------------
__global__ void maxpool_kernel(int sel_in, int layer, int sel_out)
{
    const float* hin = sel_in==0 ? g_h1 : g_h2;
    float* xout = sel_out==0 ? g_x1 : (sel_out==1 ? g_x2 : g_x3);
    int tid=threadIdx.x;
    int o = tid&63;
    int bn = blockIdx.x*4 + (tid>>6);
    float sc = g_scale[layer*1024+o], sh = g_shift[layer*1024+o];
    const float* p = hin + (size_t)bn*KK*64 + o;
    float m = -3.4e38f;
#pragma unroll
    for (int k=0;k<KK;k++){
        float v = p[k*64]*sc+sh;
        v = v>0.f ? v : 0.2f*v;
        m = fmaxf(m,v);
    }
    xout[((size_t)bn<<6)+o]=m;
}

// ---------------- BN+lrelu + transpose (b,n,o) -> (b,o,n) into d_out ----------------
__global__ void final_y_kernel(float* __restrict__ out)
{
    __shared__ float tile[32][33];
    int b = blockIdx.z;
    int n0 = blockIdx.x<<5, o0 = blockIdx.y<<5;
    int tx = threadIdx.x, ty = threadIdx.y;
    float sc = g_scale[5*1024+o0+tx], sh = g_shift[5*1024+o0+tx];
#pragma unroll
    for (int r=0;r<4;r++){
        int n = n0+ty+(r<<3);
        float v = g_ypre[(size_t)(b*NN+n)*1024 + o0+tx]*sc+sh;
        v = v>0.f ? v : 0.2f*v;
        tile[ty+(r<<3)][tx]=v;
    }
    __syncthreads();
#pragma unroll
    for (int r=0;r<4;r++){
        int o = o0+ty+(r<<3);
        out[(size_t)b*NN*1024 + (size_t)o*NN + n0+tx] = tile[tx][ty+(r<<3)];
    }
}

// ---------------- argmax / max over N per (b, channel) ----------------
__global__ void pool_kernel(float* __restrict__ out)
{
    int bo = blockIdx.x;
    const float* row = out + (size_t)bo*NN;
    int tid=threadIdx.x;
    float best=-3.4e38f; int bidx=0x7fffffff;
    for (int n=tid;n<NN;n+=256){
        float v=row[n];
        if (v>best){best=v;bidx=n;}
    }
    __shared__ float sv[256]; __shared__ int si[256];
    sv[tid]=best; si[tid]=bidx;
    __syncthreads();
    for (int s=128;s>0;s>>=1){
        if (tid<s){
            float v2=sv[tid+s]; int i2=si[tid+s];
            if (v2>sv[tid] || (v2==sv[tid] && i2<si[tid])){ sv[tid]=v2; si[tid]=i2; }
        }
        __syncthreads();
    }
    if (tid==0){
        out[(size_t)BB*1024*NN + bo]            = (float)si[0];
        out[(size_t)BB*1024*NN + BB*1024 + bo]  = sv[0];
    }
}

// ---------------- launch ----------------
extern "C" void kernel_launch(void* const* d_in, const int* in_sizes, int n_in,
                              void* d_out, int out_size)
{
    const float* x  = (const float*)d_in[0];
    const float* W1 = (const float*)d_in[1];
    const float* W2 = (const float*)d_in[2];
    const float* W3 = (const float*)d_in[3];
    const float* W4 = (const float*)d_in[4];
    const float* W5 = (const float*)d_in[5];
    const float* W6 = (const float*)d_in[6];
    const float* g1=(const float*)d_in[7];  const float* b1=(const float*)d_in[8];
    const float* g2=(const float*)d_in[9];  const float* b2=(const float*)d_in[10];
    const float* g3=(const float*)d_in[11]; const float* b3=(const float*)d_in[12];
    const float* g4=(const float*)d_in[13]; const float* b4=(const float*)d_in[14];
    const float* g5=(const float*)d_in[15]; const float* b5=(const float*)d_in[16];
    const float* g6=(const float*)d_in[17]; const float* b6=(const float*)d_in[18];
    float* out = (float*)d_out;

    const float invE = 1.0f/(float)NEg;
    const float invR = 1.0f/(float)(BB*NN);
    dim3 kg(16,16);

    zero_acc_kernel<<<48,256>>>();

    // block 1
    sqx_kernel<<<BB*NN/256,256>>>(x);
    knn_kernel<3><<<kg,128>>>(x, 0, 3*NN, 1, NN);
    conv1_kernel<<<NEg/64,256>>>(x, W1);
    stats_kernel<<<1024,256>>>(0, 0, NEg*64/4, 16);
    finalize_kernel<<<1,64>>>(0, g1, b1, invE, 64);
    conv_gemm64_kernel<<<NEg/64,256>>>(0, 0, W2, 1);
    stats_kernel<<<1024,256>>>(1, 1, NEg*64/4, 16);
    finalize_kernel<<<1,64>>>(1, g2, b2, invE, 64);
    maxpool_kernel<<<BB*NN/4,256>>>(1, 1, 0);                 // -> x1

    // block 2
    sq64_kernel<<<BB*NN/128,128>>>(1);
    knn_kernel<64><<<kg,128>>>(nullptr, 1, NN*64, 64, 1);
    conv_edge128_kernel<<<NEg/64,256>>>(1, W3);               // -> h1
    stats_kernel<<<1024,256>>>(0, 2, NEg*64/4, 16);
    finalize_kernel<<<1,64>>>(2, g3, b3, invE, 64);
    conv_gemm64_kernel<<<NEg/64,256>>>(0, 2, W4, 1);          // -> h2
    stats_kernel<<<1024,256>>>(1, 3, NEg*64/4, 16);
    finalize_kernel<<<1,64>>>(3, g4, b4, invE, 64);
    maxpool_kernel<<<BB*NN/4,256>>>(1, 3, 1);                 // -> x2

    // block 3
    sq64_kernel<<<BB*NN/128,128>>>(2);
    knn_kernel<64><<<kg,128>>>(nullptr, 2, NN*64, 64, 1);
    conv_edge128_kernel<<<NEg/64,256>>>(2, W5);               // -> h1
    stats_kernel<<<1024,256>>>(0, 4, NEg*64/4, 16);
    finalize_kernel<<<1,64>>>(4, g5, b5, invE, 64);
    maxpool_kernel<<<BB*NN/4,256>>>(0, 4, 2);                 // -> x3

    // head
    conv6_kernel<<<dim3(BB*NN/64,16),256>>>(W6);              // -> ypre
    stats_kernel<<<1024,256>>>(2, 5, BB*NN*1024/4, 256);
    finalize_kernel<<<4,256>>>(5, g6, b6, invR, 1024);
    final_y_kernel<<<dim3(NN/32, 1024/32, BB), dim3(32,8)>>>(out);
    pool_kernel<<<BB*1024,256>>>(out);
}

// round 5
// speedup vs baseline: 1.8583x; 1.8583x over previous
#include <cuda_runtime.h>

#define BB 16
#define NN 2048
#define KK 20
#define KC 26               // phase-A candidate count (margin 6)
#define NEg (BB*NN*KK)      // 655360 edges
#define EPSV 1e-5f

// ---------------- scratch (static device allocations) ----------------
__device__ float g_h1[41943040];          // NEg*64
__device__ float g_h2[41943040];
__device__ int   g_idx[NEg];
__device__ float g_x1[BB*NN*64];
__device__ float g_x2[BB*NN*64];
__device__ float g_x3[BB*NN*64];
__device__ float g_sq[BB*NN];
__device__ float g_ypre[33554432];        // B*N*1024
__device__ double g_acc[6*2048];          // per layer: sum[ C ], sumsq[ C ]
__device__ float g_scale[6*1024];
__device__ float g_shift[6*1024];

__global__ void zero_acc_kernel() {
    int i = blockIdx.x*256 + threadIdx.x;
    if (i < 6*2048) g_acc[i] = 0.0;
}

// squared norms from raw x (B,3,N), fp32 (phase-A screening only)
__global__ void sqx_kernel(const float* __restrict__ x){
    int i = blockIdx.x*256 + threadIdx.x;           // i = b*NN + n
    if (i < BB*NN){
        int b = i >> 11, n = i & (NN-1);
        const float* xb = x + (size_t)b*3*NN;
        float a=xb[n], c=xb[NN+n], d=xb[2*NN+n];
        g_sq[i] = a*a + c*c + d*d;
    }
}

// squared norms from 64-channel point features, fp32 (phase-A screening only)
__global__ void sq64_kernel(int sel){
    const float* pts = (sel==1) ? g_x1 : g_x2;
    int i = blockIdx.x*128 + threadIdx.x;           // point index
    if (i < BB*NN){
        const float4* p = reinterpret_cast<const float4*>(pts + ((size_t)i<<6));
        float s = 0.f;
#pragma unroll
        for (int q=0;q<16;q++){
            float4 v = p[q];
            s += v.x*v.x + v.y*v.y + v.z*v.z + v.w*v.w;
        }
        g_sq[i] = s;
    }
}

// ---------------- KNN two-phase ----------------
// Phase A: fp32 screen top-26 by d' = 2*dot - |q|^2  (rank-equal to full metric)
//          - query comps p[] register-resident (static access only)
//          - branchless fully-unrolled insertion (registers only)
//          - 4 independent FMA accumulators (ILP)
// Phase B: exact fp64 rescoring of the 26 candidates, top-20 SET by rank count
//          (order irrelevant downstream: max over k is permutation-invariant)
template<int C>
__global__ void knn_kernel(const float* __restrict__ ext, int sel, int sB, int sN, int sC)
{
    const float* pts = (sel==0) ? ext : (sel==1 ? g_x1 : g_x2);
    __shared__ float tile[128][(C==3)?4:68];
    __shared__ float sqs[128];
    int b = blockIdx.y;
    int row = blockIdx.x*128 + threadIdx.x;
    const float* base = pts + (size_t)b * sB;
    const float* sqb  = g_sq + (size_t)b * NN;

    float p[C];
#pragma unroll
    for (int c=0;c<C;c++) p[c] = base[(size_t)row*sN + (size_t)c*sC];

    float bd[KC]; int bi[KC];
#pragma unroll
    for (int i=0;i<KC;i++){ bd[i]=-3.4e38f; bi[i]=0; }
    float worst = -3.4e38f;

    for (int t=0;t<NN;t+=128) {
        __syncthreads();
        if (C==3) {
            for (int i=threadIdx.x;i<128*3;i+=128){
                int c=i>>7, col=i&127;
                tile[col][c] = base[(size_t)(t+col)*sN + (size_t)c*sC];
            }
        } else {
            for (int i=threadIdx.x;i<128*C;i+=128){
                int col=i/C, c=i-col*C;
                tile[col][c] = base[(size_t)(t+col)*sN + (size_t)c*sC];
            }
        }
        sqs[threadIdx.x] = sqb[t+threadIdx.x];
        __syncthreads();
#pragma unroll 1
        for (int j=0;j<128;j++) {
            float d;
            if (C==3) {
                d = 2.f*(p[0]*tile[j][0]+p[1]*tile[j][1]+p[2]*tile[j][2]) - sqs[j];
            } else {
                float d0=0.f,d1=0.f,d2=0.f,d3=0.f;
#pragma unroll
                for (int cq=0;cq<C/4;cq++){
                    float4 tv = *reinterpret_cast<const float4*>(&tile[j][cq*4]);
                    d0 += p[cq*4+0]*tv.x; d1 += p[cq*4+1]*tv.y;
                    d2 += p[cq*4+2]*tv.z; d3 += p[cq*4+3]*tv.w;
                }
                d = 2.f*((d0+d1)+(d2+d3)) - sqs[j];
            }
            if (d > worst) {
                int jj = t + j;
                bool top = (bd[0] < d);
#pragma unroll
                for (int s=KC-1; s>=1; s--){
                    float a    = bd[s-1];          // original (not yet written)
                    int   ai   = bi[s-1];
                    float self = bd[s];            // original
                    bool shift = (a < d);          // slot s-1 slides down into s
                    bool place = (!shift) && (self < d);  // d lands in slot s
                    bd[s] = place ? d  : (shift ? a  : self);
                    bi[s] = place ? jj : (shift ? ai : bi[s]);
                }
                if (top){ bd[0]=d; bi[0]=jj; }
                worst = bd[KC-1];
            }
        }
    }

    // ---- phase B: exact (double) rescoring; dynamic indexing confined to
    //      spill-friendly copies so p[]/bd[]/bi[] stay register-resident ----
    int cbi[KC];
#pragma unroll
    for (int i=0;i<KC;i++) cbi[i]=bi[i];

    double dv[KC];
#pragma unroll 1
    for (int i=0;i<KC;i++){
        int q = cbi[i];
        double dot=0.0, qsq=0.0;
#pragma unroll 4
        for (int c=0;c<C;c++){
            double qv = (double)base[(size_t)q*sN + (size_t)c*sC];
            double pv = (double)base[(size_t)row*sN + (size_t)c*sC];  // L1-hot
            dot = fma(pv, qv, dot);
            qsq = fma(qv, qv, qsq);
        }
        dv[i] = 2.0*dot - qsq;
    }

    int* o = g_idx + ((size_t)b*NN + row)*KK;
    int outn = 0;
#pragma unroll 1
    for (int i=0;i<KC;i++){
        double di = dv[i]; int ii = cbi[i];
        int cnt = 0;
#pragma unroll 1
        for (int k2=0;k2<KC;k2++){
            double dk = dv[k2];
            bool gt = (dk > di) || (dk == di && cbi[k2] < ii);
            cnt += gt ? 1 : 0;
        }
        if (cnt < KK){ o[outn] = ii; outn++; }
    }
}

// ---------------- conv1: edge feature (6) -> 64, from raw x (B,3,N) ----------------
__global__ void conv1_kernel(const float* __restrict__ x, const float* __restrict__ W1)
{
    __shared__ float f[64][6];
    int tid = threadIdx.x;
    int eb = blockIdx.x*64;
    for (int i=tid;i<384;i+=256){
        int el = i/6, c = i-el*6;
        int e = eb + el;
        int bn = e/KK;
        int n = bn & (NN-1);
        int b = bn >> 11;
        const float* xb = x + (size_t)b*3*NN;
        float v;
        if (c<3){ int nb = g_idx[e]; v = xb[c*NN+nb]-xb[c*NN+n]; }
        else    { v = xb[(c-3)*NN+n]; }
        f[el][c]=v;
    }
    int o = tid & 63;
    int eg = tid >> 6;
    float w0=W1[o*6+0],w1=W1[o*6+1],w2=W1[o*6+2],w3=W1[o*6+3],w4=W1[o*6+4],w5=W1[o*6+5];
    __syncthreads();
    for (int r=0;r<16;r++){
        int el = eg*16+r;
        float s = f[el][0]*w0+f[el][1]*w1+f[el][2]*w2+f[el][3]*w3+f[el][4]*w4+f[el][5]*w5;
        g_h1[((size_t)(eb+el)<<6)+o]=s;
    }
}

// ---------------- GEMM 64->64 with fused BN+lrelu on the input ----------------
__global__ void conv_gemm64_kernel(int sel_in, int layer, const float* __restrict__ W, int sel_out)
{
    const float* hin  = sel_in==0 ? g_h1 : g_h2;
    float* hout       = sel_out==0 ? g_h1 : g_h2;
    const float* scale = g_scale + layer*1024;
    const float* shift = g_shift + layer*1024;
    __shared__ float As[64][65];
    __shared__ float Ws[64][65];
    int tid = threadIdx.x;
    int eb = blockIdx.x*64;
    for (int i=tid;i<4096;i+=256){ int o=i>>6,k=i&63; Ws[k][o]=W[(o<<6)+k]; }
    for (int i=tid;i<4096;i+=256){
        int e=i>>6,k=i&63;
        float v = hin[((size_t)(eb+e)<<6)+k]*scale[k]+shift[k];
        As[k][e] = v>0.f ? v : 0.2f*v;
    }
    __syncthreads();
    int tx=tid&15, ty=tid>>4;
    float acc[4][4];
#pragma unroll
    for (int j=0;j<4;j++){
#pragma unroll
        for (int i=0;i<4;i++) acc[j][i]=0.f;
    }
#pragma unroll 8
    for (int k=0;k<64;k++){
        float a0=As[k][ty*4+0],a1=As[k][ty*4+1],a2=As[k][ty*4+2],a3=As[k][ty*4+3];
        float b0=Ws[k][tx*4+0],b1=Ws[k][tx*4+1],b2=Ws[k][tx*4+2],b3=Ws[k][tx*4+3];
        acc[0][0]+=a0*b0; acc[0][1]+=a0*b1; acc[0][2]+=a0*b2; acc[0][3]+=a0*b3;
        acc[1][0]+=a1*b0; acc[1][1]+=a1*b1; acc[1][2]+=a1*b2; acc[1][3]+=a1*b3;
        acc[2][0]+=a2*b0; acc[2][1]+=a2*b1; acc[2][2]+=a2*b2; acc[2][3]+=a2*b3;
        acc[3][0]+=a3*b0; acc[3][1]+=a3*b1; acc[3][2]+=a3*b2; acc[3][3]+=a3*b3;
    }
#pragma unroll
    for (int j=0;j<4;j++){
        float4 v = make_float4(acc[j][0],acc[j][1],acc[j][2],acc[j][3]);
        *reinterpret_cast<float4*>(&hout[((size_t)(eb+ty*4+j)<<6)+(tx<<2)]) = v;
    }
}

// ---------------- GEMM: edge feature (128, gathered on the fly) -> 64 ----------------
__global__ void conv_edge128_kernel(int sel_pts, const float* __restrict__ W)
{
    const float* pts = sel_pts==1 ? g_x1 : g_x2;
    __shared__ float As[64][65];
    __shared__ float Ws[64][65];
    __shared__ int s_cen[64], s_nbr[64];
    int tid=threadIdx.x, eb=blockIdx.x*64;
    if (tid<64){
        int e = eb+tid;
        int bn = e/KK;
        s_cen[tid]=bn;
        s_nbr[tid]=(bn & ~(NN-1)) + g_idx[e];
    }
    int tx=tid&15, ty=tid>>4;
    float acc[4][4];
#pragma unroll
    for (int j=0;j<4;j++){
#pragma unroll
        for (int i=0;i<4;i++) acc[j][i]=0.f;
    }
    for (int half=0; half<2; half++){
        __syncthreads();
        for (int i=tid;i<4096;i+=256){ int o=i>>6,k=i&63; Ws[k][o]=W[o*128 + (half<<6) + k]; }
        for (int i=tid;i<4096;i+=256){
            int e=i>>6,k=i&63;
            float v;
            if (half==0) v = pts[((size_t)s_nbr[e]<<6)+k] - pts[((size_t)s_cen[e]<<6)+k];
            else         v = pts[((size_t)s_cen[e]<<6)+k];
            As[k][e]=v;
        }
        __syncthreads();
#pragma unroll 8
        for (int k=0;k<64;k++){
            float a0=As[k][ty*4+0],a1=As[k][ty*4+1],a2=As[k][ty*4+2],a3=As[k][ty*4+3];
            float b0=Ws[k][tx*4+0],b1=Ws[k][tx*4+1],b2=Ws[k][tx*4+2],b3=Ws[k][tx*4+3];
            acc[0][0]+=a0*b0; acc[0][1]+=a0*b1; acc[0][2]+=a0*b2; acc[0][3]+=a0*b3;
            acc[1][0]+=a1*b0; acc[1][1]+=a1*b1; acc[1][2]+=a1*b2; acc[1][3]+=a1*b3;
            acc[2][0]+=a2*b0; acc[2][1]+=a2*b1; acc[2][2]+=a2*b2; acc[2][3]+=a2*b3;
            acc[3][0]+=a3*b0; acc[3][1]+=a3*b1; acc[3][2]+=a3*b2; acc[3][3]+=a3*b3;
        }
    }
#pragma unroll
    for (int j=0;j<4;j++){
        float4 v = make_float4(acc[j][0],acc[j][1],acc[j][2],acc[j][3]);
        *reinterpret_cast<float4*>(&g_h1[((size_t)(eb+ty*4+j)<<6)+(tx<<2)]) = v;
    }
}

// ---------------- conv6: cat[x1,x2,x3] (192) -> 1024 ----------------
__global__ void conv6_kernel(const float* __restrict__ W6)
{
    __shared__ float As[64][65];
    __shared__ float Ws[64][65];
    int tid=threadIdx.x;
    int rb = blockIdx.x*64;
    int ob = blockIdx.y*64;
    int tx=tid&15, ty=tid>>4;
    float acc[4][4];
#pragma unroll
    for (int j=0;j<4;j++){
#pragma unroll
        for (int i=0;i<4;i++) acc[j][i]=0.f;
    }
    for (int t=0;t<3;t++){
        const float* src = (t==0)? g_x1 : (t==1)? g_x2 : g_x3;
        __syncthreads();
        for (int i=tid;i<4096;i+=256){ int o=i>>6,k=i&63; Ws[k][o]=W6[(size_t)(ob+o)*192 + t*64 + k]; }
        for (int i=tid;i<4096;i+=256){ int r=i>>6,k=i&63; As[k][r]=src[((size_t)(rb+r)<<6)+k]; }
        __syncthreads();
#pragma unroll 8
        for (int k=0;k<64;k++){
            float a0=As[k][ty*4+0],a1=As[k][ty*4+1],a2=As[k][ty*4+2],a3=As[k][ty*4+3];
            float b0=Ws[k][tx*4+0],b1=Ws[k][tx*4+1],b2=Ws[k][tx*4+2],b3=Ws[k][tx*4+3];
            acc[0][0]+=a0*b0; acc[0][1]+=a0*b1; acc[0][2]+=a0*b2; acc[0][3]+=a0*b3;
            acc[1][0]+=a1*b0; acc[1][1]+=a1*b1; acc[1][2]+=a1*b2; acc[1][3]+=a1*b3;
            acc[2][0]+=a2*b0; acc[2][1]+=a2*b1; acc[2][2]+=a2*b2; acc[2][3]+=a2*b3;
            acc[3][0]+=a3*b0; acc[3][1]+=a3*b1; acc[3][2]+=a3*b2; acc[3][3]+=a3*b3;
        }
    }
#pragma unroll
    for (int j=0;j<4;j++){
        float4 v = make_float4(acc[j][0],acc[j][1],acc[j][2],acc[j][3]);
        *reinterpret_cast<float4*>(&g_ypre[(size_t)(rb+ty*4+j)*1024 + ob + (tx<<2)]) = v;
    }
}

// ---------------- per-channel sum / sumsq (double) ----------------
__global__ void stats_kernel(int sel, int layer, int n4, int Cdiv4)
{
    const float* data = sel==0 ? g_h1 : (sel==1 ? g_h2 : g_ypre);
    double* acc = g_acc + layer*2048;
    __shared__ double ss[2048];
    int C = Cdiv4<<2;
    int tid=threadIdx.x;
    for (int i=tid;i<2*C;i+=256) ss[i]=0.0;
    __syncthreads();
    int cq = (tid & (Cdiv4-1))<<2;
    double s0=0,s1=0,s2=0,s3=0,q0=0,q1=0,q2=0,q3=0;
    const float4* d4 = reinterpret_cast<const float4*>(data);
    for (int i=blockIdx.x*256+tid; i<n4; i+=gridDim.x*256){
        float4 v = d4[i];
        s0+=v.x; s1+=v.y; s2+=v.z; s3+=v.w;
        q0+=(double)v.x*v.x; q1+=(double)v.y*v.y; q2+=(double)v.z*v.z; q3+=(double)v.w*v.w;
    }
    atomicAdd(&ss[cq+0],s0); atomicAdd(&ss[cq+1],s1);
    atomicAdd(&ss[cq+2],s2); atomicAdd(&ss[cq+3],s3);
    atomicAdd(&ss[C+cq+0],q0); atomicAdd(&ss[C+cq+1],q1);
    atomicAdd(&ss[C+cq+2],q2); atomicAdd(&ss[C+cq+3],q3);
    __syncthreads();
    for (int i=tid;i<2*C;i+=256) atomicAdd(&acc[i], ss[i]);
}

__global__ void finalize_kernel(int layer, const float* __restrict__ g,
                                const float* __restrict__ bparam, float inv, int C)
{
    int c = threadIdx.x + blockIdx.x*blockDim.x;
    if (c<C){
        const double* acc = g_acc + layer*2048;
        double mean = acc[c]*(double)inv;
        double var  = acc[C+c]*(double)inv - mean*mean;
        float is = rsqrtf((float)var + EPSV)*g[c];
        g_scale[layer*1024+c]=is;
        g_shift[layer*1024+c]=bparam[c]-(float)mean*is;
    }
}

// ---------------- BN+lrelu then max over k=20 ----------------
__global__ void maxpool_kernel(int sel_in, int layer, int sel_out)
{
    const float* hin = sel_in==0 ? g_h1 : g_h2;
    float* xout = sel_out==0 ? g_x1 : (sel_out==1 ? g_x2 : g_x3);
    int tid=threadIdx.x;
    int o = tid&63;
    int bn = blockIdx.x*4 + (tid>>6);
    float sc = g_scale[layer*1024+o], sh = g_shift[layer*1024+o];
    const float* p = hin + (size_t)bn*KK*64 + o;
    float m = -3.4e38f;
#pragma unroll
    for (int k=0;k<KK;k++){
        float v = p[k*64]*sc+sh;
        v = v>0.f ? v : 0.2f*v;
        m = fmaxf(m,v);
    }
    xout[((size_t)bn<<6)+o]=m;
}

// ---------------- BN+lrelu + transpose (b,n,o) -> (b,o,n) into d_out ----------------
__global__ void final_y_kernel(float* __restrict__ out)
{
    __shared__ float tile[32][33];
    int b = blockIdx.z;
    int n0 = blockIdx.x<<5, o0 = blockIdx.y<<5;
    int tx = threadIdx.x, ty = threadIdx.y;
    float sc = g_scale[5*1024+o0+tx], sh = g_shift[5*1024+o0+tx];
#pragma unroll
    for (int r=0;r<4;r++){
        int n = n0+ty+(r<<3);
        float v = g_ypre[(size_t)(b*NN+n)*1024 + o0+tx]*sc+sh;
        v = v>0.f ? v : 0.2f*v;
        tile[ty+(r<<3)][tx]=v;
    }
    __syncthreads();
#pragma unroll
    for (int r=0;r<4;r++){
        int o = o0+ty+(r<<3);
        out[(size_t)b*NN*1024 + (size_t)o*NN + n0+tx] = tile[tx][ty+(r<<3)];
    }
}

// ---------------- argmax / max over N per (b, channel) ----------------
__global__ void pool_kernel(float* __restrict__ out)
{
    int bo = blockIdx.x;
    const float* row = out + (size_t)bo*NN;
    int tid=threadIdx.x;
    float best=-3.4e38f; int bidx=0x7fffffff;
    for (int n=tid;n<NN;n+=256){
        float v=row[n];
        if (v>best){best=v;bidx=n;}
    }
    __shared__ float sv[256]; __shared__ int si[256];
    sv[tid]=best; si[tid]=bidx;
    __syncthreads();
    for (int s=128;s>0;s>>=1){
        if (tid<s){
            float v2=sv[tid+s]; int i2=si[tid+s];
            if (v2>sv[tid] || (v2==sv[tid] && i2<si[tid])){ sv[tid]=v2; si[tid]=i2; }
        }
        __syncthreads();
    }
    if (tid==0){
        out[(size_t)BB*1024*NN + bo]            = (float)si[0];
        out[(size_t)BB*1024*NN + BB*1024 + bo]  = sv[0];
    }
}

// ---------------- launch ----------------
extern "C" void kernel_launch(void* const* d_in, const int* in_sizes, int n_in,
                              void* d_out, int out_size)
{
    const float* x  = (const float*)d_in[0];
    const float* W1 = (const float*)d_in[1];
    const float* W2 = (const float*)d_in[2];
    const float* W3 = (const float*)d_in[3];
    const float* W4 = (const float*)d_in[4];
    const float* W5 = (const float*)d_in[5];
    const float* W6 = (const float*)d_in[6];
    const float* g1=(const float*)d_in[7];  const float* b1=(const float*)d_in[8];
    const float* g2=(const float*)d_in[9];  const float* b2=(const float*)d_in[10];
    const float* g3=(const float*)d_in[11]; const float* b3=(const float*)d_in[12];
    const float* g4=(const float*)d_in[13]; const float* b4=(const float*)d_in[14];
    const float* g5=(const float*)d_in[15]; const float* b5=(const float*)d_in[16];
    const float* g6=(const float*)d_in[17]; const float* b6=(const float*)d_in[18];
    float* out = (float*)d_out;

    const float invE = 1.0f/(float)NEg;
    const float invR = 1.0f/(float)(BB*NN);
    dim3 kg(16,16);

    zero_acc_kernel<<<48,256>>>();

    // block 1
    sqx_kernel<<<BB*NN/256,256>>>(x);
    knn_kernel<3><<<kg,128>>>(x, 0, 3*NN, 1, NN);
    conv1_kernel<<<NEg/64,256>>>(x, W1);
    stats_kernel<<<1024,256>>>(0, 0, NEg*64/4, 16);
    finalize_kernel<<<1,64>>>(0, g1, b1, invE, 64);
    conv_gemm64_kernel<<<NEg/64,256>>>(0, 0, W2, 1);
    stats_kernel<<<1024,256>>>(1, 1, NEg*64/4, 16);
    finalize_kernel<<<1,64>>>(1, g2, b2, invE, 64);
    maxpool_kernel<<<BB*NN/4,256>>>(1, 1, 0);                 // -> x1

    // block 2
    sq64_kernel<<<BB*NN/128,128>>>(1);
    knn_kernel<64><<<kg,128>>>(nullptr, 1, NN*64, 64, 1);
    conv_edge128_kernel<<<NEg/64,256>>>(1, W3);               // -> h1
    stats_kernel<<<1024,256>>>(0, 2, NEg*64/4, 16);
    finalize_kernel<<<1,64>>>(2, g3, b3, invE, 64);
    conv_gemm64_kernel<<<NEg/64,256>>>(0, 2, W4, 1);          // -> h2
    stats_kernel<<<1024,256>>>(1, 3, NEg*64/4, 16);
    finalize_kernel<<<1,64>>>(3, g4, b4, invE, 64);
    maxpool_kernel<<<BB*NN/4,256>>>(1, 3, 1);                 // -> x2

    // block 3
    sq64_kernel<<<BB*NN/128,128>>>(2);
    knn_kernel<64><<<kg,128>>>(nullptr, 2, NN*64, 64, 1);
    conv_edge128_kernel<<<NEg/64,256>>>(2, W5);               // -> h1
    stats_kernel<<<1024,256>>>(0, 4, NEg*64/4, 16);
    finalize_kernel<<<1,64>>>(4, g5, b5, invE, 64);
    maxpool_kernel<<<BB*NN/4,256>>>(0, 4, 2);                 // -> x3

    // head
    conv6_kernel<<<dim3(BB*NN/64,16),256>>>(W6);              // -> ypre
    stats_kernel<<<1024,256>>>(2, 5, BB*NN*1024/4, 256);
    finalize_kernel<<<4,256>>>(5, g6, b6, invR, 1024);
    final_y_kernel<<<dim3(NN/32, 1024/32, BB), dim3(32,8)>>>(out);
    pool_kernel<<<BB*1024,256>>>(out);
}